// round 2
// baseline (speedup 1.0000x reference)
#include <cuda_runtime.h>
#include <math.h>

#define N_TOT   8192
#define BHALF   4096
#define D       128
#define STRIPES 16
#define RTILES  64

// Scratch (no device allocation allowed -> __device__ globals)
__device__ float g_W[N_TOT * D];                 // sqrt(2)-scaled normalized rows (4 MB)
__device__ float g_pos[N_TOT];                   // positive-pair similarities
__device__ float g_rowsumP[STRIPES * N_TOT];     // per-stripe partial exp-sums (deterministic reduce)

// ---------------------------------------------------------------------------
// Fast exp on the FMA pipe (avoid MUFU bottleneck: 67M exps would cost ~0.5ms
// through EX2). Magic-number round, exponent via bit tricks (no F2I), deg-5
// poly for 2^f on [-0.5,0.5], rel err ~2e-6. Valid for |s| <= ~20.
// ---------------------------------------------------------------------------
__device__ __forceinline__ float fast_exp(float s) {
    float x = s * 1.4426950408889634f;                 // s * log2(e)
    float t = __fadd_rn(x, 12582912.0f);               // magic = 1.5 * 2^23
    float f = __fsub_rn(x, __fsub_rn(t, 12582912.0f)); // fractional part
    float sc = __int_as_float((int)(((unsigned)__float_as_int(t)) << 23) + 0x3F800000);
    float p = 1.3333558146e-3f;
    p = fmaf(p, f, 9.6181291076e-3f);
    p = fmaf(p, f, 5.5504108664e-2f);
    p = fmaf(p, f, 2.4022650696e-1f);
    p = fmaf(p, f, 6.9314718056e-1f);
    p = fmaf(p, f, 1.0f);
    return sc * p;
}

// ---------------------------------------------------------------------------
// Kernel 1: normalize, scale by sqrt(2) (so dot(W_i,W_j) = sim/T directly).
// One warp per row; lane loads one float4 (32*4 = 128 = D).
// ---------------------------------------------------------------------------
__global__ void __launch_bounds__(256) k_normalize(const float* __restrict__ zi,
                                                   const float* __restrict__ zj) {
    int warp = threadIdx.x >> 5, lane = threadIdx.x & 31;
    int row = blockIdx.x * 8 + warp;
    const float* src = (row < BHALF) ? (zi + (size_t)row * D)
                                     : (zj + (size_t)(row - BHALF) * D);
    float4 v = reinterpret_cast<const float4*>(src)[lane];
    float ss = v.x * v.x + v.y * v.y + v.z * v.z + v.w * v.w;
    #pragma unroll
    for (int o = 16; o; o >>= 1) ss += __shfl_xor_sync(0xFFFFFFFFu, ss, o);
    float nrm = fmaxf(sqrtf(ss), 1e-8f);
    float sc = 1.4142135623730951f / nrm;
    float4 w = make_float4(v.x * sc, v.y * sc, v.z * sc, v.w * sc);
    reinterpret_cast<float4*>(g_W + (size_t)row * D)[lane] = w;
}

// ---------------------------------------------------------------------------
// Tile loader: 128 rows x 128 K of W -> k-major SMEM with 16B-chunk XOR
// swizzle: element (k,m) lives at S[k*128 + ((m>>2)^(k&7))*4 + (m&3)].
// Global reads are coalesced (4 rows x 128B per warp instruction); stores
// are STS.32 with 4-way conflicts (one-time cost, ~15% of block time max).
// ---------------------------------------------------------------------------
__device__ __forceinline__ void load_tile(float* __restrict__ S, int base, int tid) {
    int lane = tid & 31, warp = tid >> 5;
    int mloc = lane >> 3;            // 0..3
    int k0   = (lane & 7) << 2;      // 0,4,...,28
    #pragma unroll
    for (int it = 0; it < 4; ++it) {
        int m = it * 32 + warp * 4 + mloc;
        const float4* g = reinterpret_cast<const float4*>(g_W + (size_t)(base + m) * D);
        #pragma unroll
        for (int kk = 0; kk < 4; ++kk) {
            float4 v = g[(k0 >> 2) + kk * 8];
            int kbase = k0 + kk * 32;
            const float* vp = &v.x;
            #pragma unroll
            for (int j = 0; j < 4; ++j) {
                int kj = kbase + j;
                int chunk = (m >> 2) ^ (kj & 7);
                S[kj * 128 + chunk * 4 + (m & 3)] = vp[j];
            }
        }
    }
}

// ---------------------------------------------------------------------------
// Kernel 2: fused GEMM + exp + masked row-sum.
// Block = 128 rows x (4 tiles of 128 cols, strided by 16 stripes).
// 256 threads as 16x16, each 8x8 micro-tile, accumulators as f32x2 pairs
// driven by fma.rn.f32x2 (2x the FFMA-3reg rate on sm_103a).
// ---------------------------------------------------------------------------
extern __shared__ float smem_dyn[];

__global__ void __launch_bounds__(256, 1) k_gemm() {
    float* sA = smem_dyn;            // 128*128 floats (64 KB)
    float* sB = smem_dyn + 128 * 128;

    int tid = threadIdx.x;
    int tx = tid & 15, ty = tid >> 4;
    int stripe = blockIdx.x;
    int rowBase = blockIdx.y * 128;

    unsigned long long acc[8][4];
    float perRow[8];
    #pragma unroll
    for (int r = 0; r < 8; ++r) {
        perRow[r] = 0.0f;
        #pragma unroll
        for (int c = 0; c < 4; ++c) acc[r][c] = 0ULL;
    }

    load_tile(sA, rowBase, tid);

    const float4* A4 = reinterpret_cast<const float4*>(sA);
    const float4* B4 = reinterpret_cast<const float4*>(sB);
    int ty2 = ty * 2, tx2 = tx * 2;

    for (int t = 0; t < 4; ++t) {
        int colBase = (stripe + STRIPES * t) * 128;
        __syncthreads();                       // previous tile fully consumed
        load_tile(sB, colBase, tid);
        __syncthreads();

        #pragma unroll 1
        for (int kb = 0; kb < 128; kb += 8) {
            #pragma unroll
            for (int ku = 0; ku < 8; ++ku) {
                int k = kb + ku;                // k & 7 == ku (compile-time)
                float4 a0 = A4[k * 32 + (ty2 ^ ku)];
                float4 a1 = A4[k * 32 + ((ty2 + 1) ^ ku)];
                float4 b0 = B4[k * 32 + (tx2 ^ ku)];
                float4 b1 = B4[k * 32 + ((tx2 + 1) ^ ku)];
                unsigned long long bp0, bp1, bp2, bp3;
                asm("mov.b64 %0, {%1, %2};" : "=l"(bp0) : "f"(b0.x), "f"(b0.y));
                asm("mov.b64 %0, {%1, %2};" : "=l"(bp1) : "f"(b0.z), "f"(b0.w));
                asm("mov.b64 %0, {%1, %2};" : "=l"(bp2) : "f"(b1.x), "f"(b1.y));
                asm("mov.b64 %0, {%1, %2};" : "=l"(bp3) : "f"(b1.z), "f"(b1.w));
                float av[8] = {a0.x, a0.y, a0.z, a0.w, a1.x, a1.y, a1.z, a1.w};
                #pragma unroll
                for (int r = 0; r < 8; ++r) {
                    unsigned long long ap;
                    asm("mov.b64 %0, {%1, %1};" : "=l"(ap) : "f"(av[r]));
                    asm("fma.rn.f32x2 %0, %1, %2, %0;" : "+l"(acc[r][0]) : "l"(ap), "l"(bp0));
                    asm("fma.rn.f32x2 %0, %1, %2, %0;" : "+l"(acc[r][1]) : "l"(ap), "l"(bp1));
                    asm("fma.rn.f32x2 %0, %1, %2, %0;" : "+l"(acc[r][2]) : "l"(ap), "l"(bp2));
                    asm("fma.rn.f32x2 %0, %1, %2, %0;" : "+l"(acc[r][3]) : "l"(ap), "l"(bp3));
                }
            }
        }

        // Fused epilogue: exp + diagonal mask + per-row partial sums.
        #pragma unroll
        for (int r = 0; r < 8; ++r) {
            int grow = rowBase + ty * 8 + r;
            float rs = 0.0f;
            #pragma unroll
            for (int cp = 0; cp < 4; ++cp) {
                float lo, hi;
                asm("mov.b64 {%0, %1}, %2;" : "=f"(lo), "=f"(hi) : "l"(acc[r][cp]));
                acc[r][cp] = 0ULL;
                int c0 = colBase + tx * 8 + cp * 2;
                float e0 = fast_exp(lo);
                float e1 = fast_exp(hi);
                if (c0 != grow)     rs += e0;
                if (c0 + 1 != grow) rs += e1;
            }
            perRow[r] += rs;
        }
    }

    // Cross-thread (tx) row reduction -> per-stripe partial (no atomics).
    __syncthreads();
    #pragma unroll
    for (int r = 0; r < 8; ++r)
        sA[(ty * 8 + r) * 17 + tx] = perRow[r];
    __syncthreads();
    if (tid < 128) {
        float s = 0.0f;
        #pragma unroll
        for (int j = 0; j < 16; ++j) s += sA[tid * 17 + j];
        g_rowsumP[stripe * N_TOT + rowBase + tid] = s;
    }
}

// ---------------------------------------------------------------------------
// Kernel 3: positive-pair similarities. Warp per row.
// ---------------------------------------------------------------------------
__global__ void __launch_bounds__(256) k_pos() {
    int warp = threadIdx.x >> 5, lane = threadIdx.x & 31;
    int row = blockIdx.x * 8 + warp;
    int partner = (row < BHALF) ? (row + BHALF) : (row - BHALF);
    float4 a = reinterpret_cast<const float4*>(g_W + (size_t)row * D)[lane];
    float4 b = reinterpret_cast<const float4*>(g_W + (size_t)partner * D)[lane];
    float d = a.x * b.x + a.y * b.y + a.z * b.z + a.w * b.w;
    #pragma unroll
    for (int o = 16; o; o >>= 1) d += __shfl_xor_sync(0xFFFFFFFFu, d, o);
    if (lane == 0) g_pos[row] = d;
}

// ---------------------------------------------------------------------------
// Kernel 4: final deterministic reduction: mean(log(sum_partials) - pos).
// ---------------------------------------------------------------------------
__global__ void __launch_bounds__(256) k_reduce(float* __restrict__ out) {
    __shared__ float red[256];
    float acc = 0.0f;
    for (int i = threadIdx.x; i < N_TOT; i += 256) {
        float s = 0.0f;
        #pragma unroll
        for (int p = 0; p < STRIPES; ++p) s += g_rowsumP[p * N_TOT + i];
        acc += logf(s) - g_pos[i];
    }
    red[threadIdx.x] = acc;
    __syncthreads();
    #pragma unroll
    for (int o = 128; o; o >>= 1) {
        if (threadIdx.x < o) red[threadIdx.x] += red[threadIdx.x + o];
        __syncthreads();
    }
    if (threadIdx.x == 0) out[0] = red[0] * (1.0f / (float)N_TOT);
}

// ---------------------------------------------------------------------------
extern "C" void kernel_launch(void* const* d_in, const int* in_sizes, int n_in,
                              void* d_out, int out_size) {
    const float* zi = (const float*)d_in[0];
    const float* zj = (const float*)d_in[1];
    float* out = (float*)d_out;

    // 128 KB dynamic smem for the GEMM (not a stream op; capture-safe).
    cudaFuncSetAttribute(k_gemm, cudaFuncAttributeMaxDynamicSharedMemorySize, 131072);

    k_normalize<<<N_TOT / 8, 256>>>(zi, zj);
    k_gemm<<<dim3(STRIPES, RTILES), 256, 131072>>>();
    k_pos<<<N_TOT / 8, 256>>>();
    k_reduce<<<1, 256>>>(out);
}

// round 6
// speedup vs baseline: 5.8614x; 5.8614x over previous
#include <cuda_runtime.h>
#include <cuda_bf16.h>
#include <stdint.h>
#include <math.h>

#define N_TOT   8192
#define BHALF   4096
#define DD      128
#define T_TILES 32

// ---- scratch ---------------------------------------------------------------
__device__ __nv_bfloat16 g_Wb[N_TOT * DD];   // sqrt(2)-scaled normalized rows (2 MB)
__device__ float g_pos[N_TOT];
__device__ float g_rowsumP[2 * N_TOT];
__device__ float g_blocksum[64];

// ---- helpers ---------------------------------------------------------------
__device__ __forceinline__ uint32_t smem_u32(const void* p) {
    uint32_t a;
    asm("{ .reg .u64 t; cvta.to.shared.u64 t, %1; cvt.u32.u64 %0, t; }" : "=r"(a) : "l"(p));
    return a;
}

__device__ __forceinline__ void ldsm_x4(uint32_t* r, uint32_t addr) {
    asm volatile("ldmatrix.sync.aligned.m8n8.x4.shared.b16 {%0,%1,%2,%3}, [%4];"
                 : "=r"(r[0]), "=r"(r[1]), "=r"(r[2]), "=r"(r[3]) : "r"(addr));
}

__device__ __forceinline__ void mma16816(float* c, const uint32_t* a, uint32_t b0, uint32_t b1) {
    asm volatile("mma.sync.aligned.m16n8k16.row.col.f32.bf16.bf16.f32 "
                 "{%0,%1,%2,%3}, {%4,%5,%6,%7}, {%8,%9}, {%0,%1,%2,%3};"
                 : "+f"(c[0]), "+f"(c[1]), "+f"(c[2]), "+f"(c[3])
                 : "r"(a[0]), "r"(a[1]), "r"(a[2]), "r"(a[3]), "r"(b0), "r"(b1));
}

#define CP_COMMIT() asm volatile("cp.async.commit_group;" ::: "memory")
#define CP_WAIT0()  asm volatile("cp.async.wait_group 0;" ::: "memory")

// async copy of a 128x128 bf16 tile (row-major, 256B rows) with 16B-chunk
// XOR swizzle: chunk c of row r lands at c ^ (r & 7).
__device__ __forceinline__ void cp_tile(uint32_t dstBase, int gRow, int tid) {
    const char* src = (const char*)g_Wb + (size_t)gRow * 256;
    #pragma unroll
    for (int i = 0; i < 8; ++i) {
        int idx = tid + i * 256;
        int row = idx >> 4, c = idx & 15;
        uint32_t d = dstBase + row * 256 + ((c ^ (row & 7)) << 4);
        const char* s = src + row * 256 + c * 16;
        asm volatile("cp.async.cg.shared.global [%0], [%1], 16;" :: "r"(d), "l"(s) : "memory");
    }
}

// ---------------------------------------------------------------------------
// Kernel 1: normalize + sqrt(2)-scale -> bf16. Warp per row.
// ---------------------------------------------------------------------------
__global__ void __launch_bounds__(256) k_normalize(const float* __restrict__ zi,
                                                   const float* __restrict__ zj) {
    int warp = threadIdx.x >> 5, lane = threadIdx.x & 31;
    int row = blockIdx.x * 8 + warp;
    const float* src = (row < BHALF) ? (zi + (size_t)row * DD)
                                     : (zj + (size_t)(row - BHALF) * DD);
    float4 v = reinterpret_cast<const float4*>(src)[lane];
    float ss = v.x * v.x + v.y * v.y + v.z * v.z + v.w * v.w;
    #pragma unroll
    for (int o = 16; o; o >>= 1) ss += __shfl_xor_sync(0xFFFFFFFFu, ss, o);
    float sc = 1.4142135623730951f / fmaxf(sqrtf(ss), 1e-8f);
    __nv_bfloat162 p0 = __floats2bfloat162_rn(v.x * sc, v.y * sc);
    __nv_bfloat162 p1 = __floats2bfloat162_rn(v.z * sc, v.w * sc);
    uint2 out;
    out.x = *reinterpret_cast<uint32_t*>(&p0);
    out.y = *reinterpret_cast<uint32_t*>(&p1);
    reinterpret_cast<uint2*>(g_Wb + (size_t)row * DD)[lane] = out;
}

// ---------------------------------------------------------------------------
// Kernel 2: HMMA Gram + fused exp + masked row-sum.
// Grid (2 halves, 64 row-tiles), 256 thr = 8 warps as 2(M) x 4(N).
// Warp tile 64x32: 4 m-frags x 4 n-frags of m16n8k16.
// ---------------------------------------------------------------------------
extern __shared__ char smem_g[];

__global__ void __launch_bounds__(256, 1) k_gemm() {
    uint32_t sA = smem_u32(smem_g);
    uint32_t sB0 = sA + 32768, sB1 = sA + 65536;

    int tid = threadIdx.x, lane = tid & 31, wid = tid >> 5;
    int warpM = wid >> 2;          // 0..1
    int warpN = wid & 3;           // 0..3
    int h = blockIdx.x;
    int rowBase = blockIdx.y * 128;

    // ldmatrix lane address patterns
    int aRow = lane & 15;                  // A: lanes 0-15 rows, 16-31 rows (k+8)
    int aK   = (lane >> 4) << 3;
    int bJ   = (lane & 7) + ((lane >> 4) << 3);   // B: (j-lo,k-lo),(j-lo,k-hi),(j-hi,k-lo),(j-hi,k-hi)
    int bK   = ((lane >> 3) & 1) << 3;

    // prologue: A tile + B tile 0
    cp_tile(sA, rowBase, tid);
    cp_tile(sB0, h * 4096, tid);
    CP_COMMIT();
    CP_WAIT0();
    __syncthreads();

    float rAcc[8];
    #pragma unroll
    for (int i = 0; i < 8; ++i) rAcc[i] = 0.0f;

    // precomputed A ldmatrix byte offsets (per mi, per ks, lane-dependent)
    int aRowG = warpM * 64 + aRow;         // + mi*16
    int bJG   = warpN * 32 + bJ;           // + nj*16

    for (int t = 0; t < T_TILES; ++t) {
        uint32_t cb = (t & 1) ? sB1 : sB0;
        if (t + 1 < T_TILES) {
            cp_tile((t & 1) ? sB0 : sB1, h * 4096 + (t + 1) * 128, tid);
            CP_COMMIT();
        }

        float c[4][4][4];
        #pragma unroll
        for (int mi = 0; mi < 4; ++mi)
            #pragma unroll
            for (int nf = 0; nf < 4; ++nf)
                #pragma unroll
                for (int q = 0; q < 4; ++q) c[mi][nf][q] = 0.0f;

        #pragma unroll
        for (int ks = 0; ks < 8; ++ks) {
            uint32_t a[4][4], b[2][4];
            #pragma unroll
            for (int mi = 0; mi < 4; ++mi) {
                int r = aRowG + mi * 16;
                int k = ks * 16 + aK;
                ldsm_x4(a[mi], sA + r * 256 + (((k >> 3) ^ (r & 7)) << 4));
            }
            #pragma unroll
            for (int nj = 0; nj < 2; ++nj) {
                int j = bJG + nj * 16;
                int k = ks * 16 + bK;
                ldsm_x4(b[nj], cb + j * 256 + (((k >> 3) ^ (j & 7)) << 4));
            }
            #pragma unroll
            for (int mi = 0; mi < 4; ++mi) {
                mma16816(c[mi][0], a[mi], b[0][0], b[0][1]);
                mma16816(c[mi][1], a[mi], b[0][2], b[0][3]);
                mma16816(c[mi][2], a[mi], b[1][0], b[1][1]);
                mma16816(c[mi][3], a[mi], b[1][2], b[1][3]);
            }
        }

        // fused epilogue: exp, mask diagonal, accumulate per-row sums
        int colT = h * 4096 + t * 128 + warpN * 32 + (lane & 3) * 2;
        int rT = rowBase + warpM * 64 + (lane >> 2);
        #pragma unroll
        for (int mi = 0; mi < 4; ++mi) {
            int r0 = rT + mi * 16, r1 = r0 + 8;
            float s0 = 0.f, s1 = 0.f;
            #pragma unroll
            for (int nf = 0; nf < 4; ++nf) {
                int c0 = colT + nf * 8;
                float e0 = __expf(c[mi][nf][0]);
                float e1 = __expf(c[mi][nf][1]);
                float e2 = __expf(c[mi][nf][2]);
                float e3 = __expf(c[mi][nf][3]);
                s0 += (c0 != r0)     ? e0 : 0.f;
                s0 += (c0 + 1 != r0) ? e1 : 0.f;
                s1 += (c0 != r1)     ? e2 : 0.f;
                s1 += (c0 + 1 != r1) ? e3 : 0.f;
            }
            rAcc[mi * 2]     += s0;
            rAcc[mi * 2 + 1] += s1;
        }

        if (t + 1 < T_TILES) CP_WAIT0();
        __syncthreads();
    }

    // cross-warp row reduction (reuse smem; all compute done)
    float* sRed = (float*)smem_g;           // [128][17]
    #pragma unroll
    for (int mi = 0; mi < 4; ++mi) {
        #pragma unroll
        for (int hf = 0; hf < 2; ++hf) {
            int r = warpM * 64 + mi * 16 + (lane >> 2) + hf * 8;
            sRed[r * 17 + warpN * 4 + (lane & 3)] = rAcc[mi * 2 + hf];
        }
    }
    __syncthreads();
    if (tid < 128) {
        float s = 0.0f;
        #pragma unroll
        for (int j = 0; j < 16; ++j) s += sRed[tid * 17 + j];
        g_rowsumP[h * N_TOT + rowBase + tid] = s;
    }
}

// ---------------------------------------------------------------------------
// Kernel 3: positive-pair logits, exact fp32 from raw inputs.
// ---------------------------------------------------------------------------
__global__ void __launch_bounds__(256) k_pos(const float* __restrict__ zi,
                                             const float* __restrict__ zj) {
    int warp = threadIdx.x >> 5, lane = threadIdx.x & 31;
    int r = blockIdx.x * 8 + warp;
    float4 a = reinterpret_cast<const float4*>(zi + (size_t)r * DD)[lane];
    float4 b = reinterpret_cast<const float4*>(zj + (size_t)r * DD)[lane];
    float aa = a.x * a.x + a.y * a.y + a.z * a.z + a.w * a.w;
    float bb = b.x * b.x + b.y * b.y + b.z * b.z + b.w * b.w;
    float ab = a.x * b.x + a.y * b.y + a.z * b.z + a.w * b.w;
    #pragma unroll
    for (int o = 16; o; o >>= 1) {
        aa += __shfl_xor_sync(0xFFFFFFFFu, aa, o);
        bb += __shfl_xor_sync(0xFFFFFFFFu, bb, o);
        ab += __shfl_xor_sync(0xFFFFFFFFu, ab, o);
    }
    if (lane == 0) {
        float p = 2.0f * ab / (fmaxf(sqrtf(aa), 1e-8f) * fmaxf(sqrtf(bb), 1e-8f));
        g_pos[r] = p;
        g_pos[r + BHALF] = p;
    }
}

// ---------------------------------------------------------------------------
// Kernel 4/5: deterministic two-stage final reduction.
// ---------------------------------------------------------------------------
__global__ void __launch_bounds__(128) k_final1() {
    __shared__ float red[128];
    int row = blockIdx.x * 128 + threadIdx.x;
    float s = g_rowsumP[row] + g_rowsumP[N_TOT + row];
    red[threadIdx.x] = logf(s) - g_pos[row];
    __syncthreads();
    #pragma unroll
    for (int o = 64; o; o >>= 1) {
        if (threadIdx.x < o) red[threadIdx.x] += red[threadIdx.x + o];
        __syncthreads();
    }
    if (threadIdx.x == 0) g_blocksum[blockIdx.x] = red[0];
}

__global__ void __launch_bounds__(64) k_final2(float* __restrict__ out) {
    __shared__ float red[64];
    red[threadIdx.x] = g_blocksum[threadIdx.x];
    __syncthreads();
    #pragma unroll
    for (int o = 32; o; o >>= 1) {
        if (threadIdx.x < o) red[threadIdx.x] += red[threadIdx.x + o];
        __syncthreads();
    }
    if (threadIdx.x == 0) out[0] = red[0] * (1.0f / (float)N_TOT);
}

// ---------------------------------------------------------------------------
extern "C" void kernel_launch(void* const* d_in, const int* in_sizes, int n_in,
                              void* d_out, int out_size) {
    const float* zi = (const float*)d_in[0];
    const float* zj = (const float*)d_in[1];
    float* out = (float*)d_out;

    cudaFuncSetAttribute(k_gemm, cudaFuncAttributeMaxDynamicSharedMemorySize, 98304);

    k_normalize<<<N_TOT / 8, 256>>>(zi, zj);
    k_gemm<<<dim3(2, 64), 256, 98304>>>();
    k_pos<<<BHALF / 8, 256>>>(zi, zj);
    k_final1<<<64, 128>>>();
    k_final2<<<1, 64>>>(out);
}